// round 2
// baseline (speedup 1.0000x reference)
#include <cuda_runtime.h>
#include <stdint.h>

#define N_NODES 100000
#define N_EDGES 3200000
#define F 128           // hidden width (all layers output 128)
#define T_POINTS 4

// ---- scratch (no allocations allowed => device globals) ----
__device__ float g_support[(size_t)N_NODES * F];   // 51.2 MB
__device__ float g_h[(size_t)N_NODES * F];         // 51.2 MB
__device__ int   g_rowptr[N_NODES + 1];
__device__ int   g_deg[N_NODES];
__device__ int   g_cursor[N_NODES];
__device__ uint2 g_csr[N_EDGES];                   // {src col, val bits} 25.6 MB

// ---------------------------------------------------------------------------
// CSR build: histogram -> single-block scan -> scatter
// ---------------------------------------------------------------------------
__global__ void __launch_bounds__(256, 1) k_zero_counts() {
    int i = blockIdx.x * blockDim.x + threadIdx.x;
    if (i < N_NODES) { g_deg[i] = 0; g_cursor[i] = 0; }
}

__global__ void __launch_bounds__(256, 1) k_hist(const int* __restrict__ ei) {
    int e = blockIdx.x * blockDim.x + threadIdx.x;
    if (e < N_EDGES) atomicAdd(&g_deg[ei[e]], 1);   // ei[e] = dst row
}

__global__ void __launch_bounds__(1024, 1) k_scan() {
    __shared__ int sums[1024];
    const int tid = threadIdx.x;
    const int PER = (N_NODES + 1023) / 1024;        // 98
    const int base = tid * PER;
    int s = 0;
    #pragma unroll 1
    for (int i = 0; i < PER; i++) {
        int idx = base + i;
        if (idx < N_NODES) s += g_deg[idx];
    }
    sums[tid] = s;
    __syncthreads();
    // Hillis-Steele inclusive scan over 1024 partials
    #pragma unroll 1
    for (int off = 1; off < 1024; off <<= 1) {
        int v = (tid >= off) ? sums[tid - off] : 0;
        __syncthreads();
        sums[tid] += v;
        __syncthreads();
    }
    int run = (tid == 0) ? 0 : sums[tid - 1];       // exclusive prefix
    #pragma unroll 1
    for (int i = 0; i < PER; i++) {
        int idx = base + i;
        if (idx < N_NODES) { g_rowptr[idx] = run; run += g_deg[idx]; }
    }
    if (tid == 0) g_rowptr[N_NODES] = N_EDGES;
}

__global__ void __launch_bounds__(256, 1)
k_scatter(const int* __restrict__ ei, const float* __restrict__ ev) {
    int e = blockIdx.x * blockDim.x + threadIdx.x;
    if (e < N_EDGES) {
        int dst = ei[e];
        int src = ei[N_EDGES + e];
        int pos = g_rowptr[dst] + atomicAdd(&g_cursor[dst], 1);
        g_csr[pos] = make_uint2((unsigned)src, __float_as_uint(ev[e]));
    }
}

// ---------------------------------------------------------------------------
// fp32 tiled GEMM: C[M,128] = A[M,K] @ B[K,128], K % 16 == 0
// block tile 128x128, 256 threads, 8x8 microtile per thread
// ---------------------------------------------------------------------------
__global__ void __launch_bounds__(256, 2)
k_gemm(const float* __restrict__ A, const float* __restrict__ B,
       float* __restrict__ C, int M, int K) {
    __shared__ float As[16][132];   // A^T staged: As[k][m]
    __shared__ float Bs[16][128];

    const int tid = threadIdx.x;
    const int blockRow = blockIdx.x * 128;
    const int ty = tid >> 4, tx = tid & 15;
    const int row0 = ty * 8, col0 = tx * 8;

    float acc[8][8] = {};

    for (int k0 = 0; k0 < K; k0 += 16) {
        #pragma unroll
        for (int l = 0; l < 2; l++) {
            int idx = tid + l * 256;            // 0..511
            // A tile: 128 rows x 16 cols, float4 per slot
            int r = idx >> 2;                   // 0..127
            int c = (idx & 3) * 4;              // 0,4,8,12
            int gr = blockRow + r;
            float4 v = make_float4(0.f, 0.f, 0.f, 0.f);
            if (gr < M)
                v = *reinterpret_cast<const float4*>(&A[(size_t)gr * K + k0 + c]);
            As[c + 0][r] = v.x; As[c + 1][r] = v.y;
            As[c + 2][r] = v.z; As[c + 3][r] = v.w;
            // B tile: 16 rows x 128 cols
            int rb = idx >> 5;                  // 0..15
            int cb = (idx & 31) * 4;            // 0..124
            *reinterpret_cast<float4*>(&Bs[rb][cb]) =
                *reinterpret_cast<const float4*>(&B[(size_t)(k0 + rb) * 128 + cb]);
        }
        __syncthreads();

        #pragma unroll
        for (int k = 0; k < 16; k++) {
            float a[8], b[8];
            *reinterpret_cast<float4*>(a)     = *reinterpret_cast<float4*>(&As[k][row0]);
            *reinterpret_cast<float4*>(a + 4) = *reinterpret_cast<float4*>(&As[k][row0 + 4]);
            *reinterpret_cast<float4*>(b)     = *reinterpret_cast<float4*>(&Bs[k][col0]);
            *reinterpret_cast<float4*>(b + 4) = *reinterpret_cast<float4*>(&Bs[k][col0 + 4]);
            #pragma unroll
            for (int i = 0; i < 8; i++)
                #pragma unroll
                for (int j = 0; j < 8; j++)
                    acc[i][j] = fmaf(a[i], b[j], acc[i][j]);
        }
        __syncthreads();
    }

    #pragma unroll
    for (int i = 0; i < 8; i++) {
        int gr = blockRow + row0 + i;
        if (gr < M) {
            *reinterpret_cast<float4*>(&C[(size_t)gr * 128 + col0]) =
                make_float4(acc[i][0], acc[i][1], acc[i][2], acc[i][3]);
            *reinterpret_cast<float4*>(&C[(size_t)gr * 128 + col0 + 4]) =
                make_float4(acc[i][4], acc[i][5], acc[i][6], acc[i][7]);
        }
    }
}

// ---------------------------------------------------------------------------
// SPMM (CSR gather) + bias + ReLU: out[r] = relu(sum_e v_e * support[col_e] + b)
// one warp per row; lane owns a float4 slice of the 128-wide feature vector
// ---------------------------------------------------------------------------
__global__ void __launch_bounds__(256, 4)
k_spmm(const float* __restrict__ support,
       const float* __restrict__ bias,
       float* __restrict__ out) {
    int gw = (blockIdx.x * blockDim.x + threadIdx.x) >> 5;
    int lane = threadIdx.x & 31;
    if (gw >= N_NODES) return;

    int e   = g_rowptr[gw];
    int end = g_rowptr[gw + 1];

    float ax = 0.f, ay = 0.f, az = 0.f, aw = 0.f;
    const int off = lane * 4;

    for (; e + 4 <= end; e += 4) {
        #pragma unroll
        for (int u = 0; u < 4; u++) {
            uint2 cv = g_csr[e + u];
            float v = __uint_as_float(cv.y);
            float4 s = *reinterpret_cast<const float4*>(&support[(size_t)cv.x * F + off]);
            ax = fmaf(v, s.x, ax); ay = fmaf(v, s.y, ay);
            az = fmaf(v, s.z, az); aw = fmaf(v, s.w, aw);
        }
    }
    for (; e < end; e++) {
        uint2 cv = g_csr[e];
        float v = __uint_as_float(cv.y);
        float4 s = *reinterpret_cast<const float4*>(&support[(size_t)cv.x * F + off]);
        ax = fmaf(v, s.x, ax); ay = fmaf(v, s.y, ay);
        az = fmaf(v, s.z, az); aw = fmaf(v, s.w, aw);
    }

    float4 b = *reinterpret_cast<const float4*>(&bias[off]);
    ax = fmaxf(ax + b.x, 0.f); ay = fmaxf(ay + b.y, 0.f);
    az = fmaxf(az + b.z, 0.f); aw = fmaxf(aw + b.w, 0.f);
    *reinterpret_cast<float4*>(&out[(size_t)gw * F + off]) = make_float4(ax, ay, az, aw);
}

// ---------------------------------------------------------------------------
extern "C" void kernel_launch(void* const* d_in, const int* in_sizes, int n_in,
                              void* d_out, int out_size) {
    const float* x  = (const float*)d_in[0];   // [100000, 256]
    const int*   ei = (const int*)  d_in[1];   // [2, 3200000]
    const float* ev = (const float*)d_in[2];   // [3200000]
    const float* W1 = (const float*)d_in[3];   // [256,128]
    const float* b1 = (const float*)d_in[4];
    const float* W2 = (const float*)d_in[5];   // [128,128]
    const float* b2 = (const float*)d_in[6];
    const float* W3 = (const float*)d_in[7];   // [128,128]
    const float* b3 = (const float*)d_in[8];
    float* out = (float*)d_out;                // [4, 100000, 128]

    float* support = nullptr;
    float* h       = nullptr;
    cudaGetSymbolAddress((void**)&support, g_support);
    cudaGetSymbolAddress((void**)&h,       g_h);

    // --- build CSR (reused by all 5 SPMMs) ---
    k_zero_counts<<<(N_NODES + 255) / 256, 256>>>();
    k_hist<<<(N_EDGES + 255) / 256, 256>>>(ei);
    k_scan<<<1, 1024>>>();
    k_scatter<<<(N_EDGES + 255) / 256, 256>>>(ei, ev);

    const int gemmGrid = (N_NODES + 127) / 128;
    const int spmmGrid = (N_NODES * 32 + 255) / 256;

    // layer 1: h = relu(spmm(x @ W1) + b1)
    k_gemm<<<gemmGrid, 256>>>(x, W1, support, N_NODES, 256);
    k_spmm<<<spmmGrid, 256>>>(support, b1, h);

    // layer 2: preds[0] = relu(spmm(h @ W2) + b2)
    k_gemm<<<gemmGrid, 256>>>(h, W2, support, N_NODES, 128);
    k_spmm<<<spmmGrid, 256>>>(support, b2, out);

    // timepoints 1..3: preds[t] = relu(spmm(preds[t-1] @ W3) + b3)
    for (int t = 1; t < T_POINTS; t++) {
        const float* prev = out + (size_t)(t - 1) * N_NODES * F;
        float* cur        = out + (size_t)t       * N_NODES * F;
        k_gemm<<<gemmGrid, 256>>>(prev, W3, support, N_NODES, 128);
        k_spmm<<<spmmGrid, 256>>>(support, b3, cur);
    }
}

// round 3
// speedup vs baseline: 1.1718x; 1.1718x over previous
#include <cuda_runtime.h>
#include <cuda_fp16.h>
#include <stdint.h>

#define N_NODES 100000
#define N_EDGES 3200000
#define F 128           // hidden width (all layers output 128)
#define T_POINTS 4

// ---- scratch (no allocations allowed => device globals) ----
__device__ __half g_support[(size_t)N_NODES * F]; // 25.6 MB (fp16 gather source)
__device__ float  g_h[(size_t)N_NODES * F];       // 51.2 MB (layer-1 intermediate)
__device__ int    g_rowptr[N_NODES + 1];
__device__ int    g_deg[N_NODES];
__device__ int    g_cursor[N_NODES];
__device__ uint2  g_csr[N_EDGES];                 // {src col, val bits} 25.6 MB

// ---------------------------------------------------------------------------
// CSR build: histogram -> single-block scan -> scatter
// ---------------------------------------------------------------------------
__global__ void __launch_bounds__(256, 1) k_zero_counts() {
    int i = blockIdx.x * blockDim.x + threadIdx.x;
    if (i < N_NODES) { g_deg[i] = 0; g_cursor[i] = 0; }
}

__global__ void __launch_bounds__(256, 1) k_hist(const int* __restrict__ ei) {
    int e = blockIdx.x * blockDim.x + threadIdx.x;
    if (e < N_EDGES) atomicAdd(&g_deg[ei[e]], 1);   // ei[e] = dst row
}

__global__ void __launch_bounds__(1024, 1) k_scan() {
    __shared__ int sums[1024];
    const int tid = threadIdx.x;
    const int PER = (N_NODES + 1023) / 1024;        // 98
    const int base = tid * PER;
    int s = 0;
    #pragma unroll 1
    for (int i = 0; i < PER; i++) {
        int idx = base + i;
        if (idx < N_NODES) s += g_deg[idx];
    }
    sums[tid] = s;
    __syncthreads();
    #pragma unroll 1
    for (int off = 1; off < 1024; off <<= 1) {
        int v = (tid >= off) ? sums[tid - off] : 0;
        __syncthreads();
        sums[tid] += v;
        __syncthreads();
    }
    int run = (tid == 0) ? 0 : sums[tid - 1];       // exclusive prefix
    #pragma unroll 1
    for (int i = 0; i < PER; i++) {
        int idx = base + i;
        if (idx < N_NODES) { g_rowptr[idx] = run; run += g_deg[idx]; }
    }
    if (tid == 0) g_rowptr[N_NODES] = N_EDGES;
}

__global__ void __launch_bounds__(256, 1)
k_scatter(const int* __restrict__ ei, const float* __restrict__ ev) {
    int e = blockIdx.x * blockDim.x + threadIdx.x;
    if (e < N_EDGES) {
        int dst = ei[e];
        int src = ei[N_EDGES + e];
        int pos = g_rowptr[dst] + atomicAdd(&g_cursor[dst], 1);
        g_csr[pos] = make_uint2((unsigned)src, __float_as_uint(ev[e]));
    }
}

// ---------------------------------------------------------------------------
// fp32 tiled GEMM -> fp16 output: C[M,128] = half(A[M,K] @ B[K,128])
// block tile 128x128, 256 threads, 8x8 microtile per thread
// ---------------------------------------------------------------------------
__global__ void __launch_bounds__(256, 2)
k_gemm(const float* __restrict__ A, const float* __restrict__ B,
       __half* __restrict__ C, int M, int K) {
    __shared__ float As[16][132];   // A^T staged: As[k][m]
    __shared__ float Bs[16][128];

    const int tid = threadIdx.x;
    const int blockRow = blockIdx.x * 128;
    const int ty = tid >> 4, tx = tid & 15;
    const int row0 = ty * 8, col0 = tx * 8;

    float acc[8][8] = {};

    for (int k0 = 0; k0 < K; k0 += 16) {
        #pragma unroll
        for (int l = 0; l < 2; l++) {
            int idx = tid + l * 256;            // 0..511
            int r = idx >> 2;                   // 0..127
            int c = (idx & 3) * 4;              // 0,4,8,12
            int gr = blockRow + r;
            float4 v = make_float4(0.f, 0.f, 0.f, 0.f);
            if (gr < M)
                v = *reinterpret_cast<const float4*>(&A[(size_t)gr * K + k0 + c]);
            As[c + 0][r] = v.x; As[c + 1][r] = v.y;
            As[c + 2][r] = v.z; As[c + 3][r] = v.w;
            int rb = idx >> 5;                  // 0..15
            int cb = (idx & 31) * 4;            // 0..124
            *reinterpret_cast<float4*>(&Bs[rb][cb]) =
                *reinterpret_cast<const float4*>(&B[(size_t)(k0 + rb) * 128 + cb]);
        }
        __syncthreads();

        #pragma unroll
        for (int k = 0; k < 16; k++) {
            float a[8], b[8];
            *reinterpret_cast<float4*>(a)     = *reinterpret_cast<float4*>(&As[k][row0]);
            *reinterpret_cast<float4*>(a + 4) = *reinterpret_cast<float4*>(&As[k][row0 + 4]);
            *reinterpret_cast<float4*>(b)     = *reinterpret_cast<float4*>(&Bs[k][col0]);
            *reinterpret_cast<float4*>(b + 4) = *reinterpret_cast<float4*>(&Bs[k][col0 + 4]);
            #pragma unroll
            for (int i = 0; i < 8; i++)
                #pragma unroll
                for (int j = 0; j < 8; j++)
                    acc[i][j] = fmaf(a[i], b[j], acc[i][j]);
        }
        __syncthreads();
    }

    #pragma unroll
    for (int i = 0; i < 8; i++) {
        int gr = blockRow + row0 + i;
        if (gr < M) {
            // pack 8 fp32 -> 8 fp16 (16B store, tx*16 byte offset => aligned)
            __half2 p0 = __floats2half2_rn(acc[i][0], acc[i][1]);
            __half2 p1 = __floats2half2_rn(acc[i][2], acc[i][3]);
            __half2 p2 = __floats2half2_rn(acc[i][4], acc[i][5]);
            __half2 p3 = __floats2half2_rn(acc[i][6], acc[i][7]);
            uint4 packed;
            packed.x = *reinterpret_cast<uint32_t*>(&p0);
            packed.y = *reinterpret_cast<uint32_t*>(&p1);
            packed.z = *reinterpret_cast<uint32_t*>(&p2);
            packed.w = *reinterpret_cast<uint32_t*>(&p3);
            *reinterpret_cast<uint4*>(&C[(size_t)gr * 128 + col0]) = packed;
        }
    }
}

// ---------------------------------------------------------------------------
// SPMM (CSR gather, fp16 source, fp32 accum) + bias + ReLU
// one warp per row; lane owns 4 features (8B gather per lane = 256B per edge)
// ---------------------------------------------------------------------------
__global__ void __launch_bounds__(256, 4)
k_spmm(const __half* __restrict__ support,
       const float* __restrict__ bias,
       float* __restrict__ out) {
    int gw = (blockIdx.x * blockDim.x + threadIdx.x) >> 5;
    int lane = threadIdx.x & 31;
    if (gw >= N_NODES) return;

    int e   = g_rowptr[gw];
    int end = g_rowptr[gw + 1];

    float ax = 0.f, ay = 0.f, az = 0.f, aw = 0.f;
    const int off = lane * 4;

    for (; e + 4 <= end; e += 4) {
        #pragma unroll
        for (int u = 0; u < 4; u++) {
            uint2 cv = g_csr[e + u];
            float v = __uint_as_float(cv.y);
            uint2 raw = *reinterpret_cast<const uint2*>(&support[(size_t)cv.x * F + off]);
            float2 f0 = __half22float2(*reinterpret_cast<__half2*>(&raw.x));
            float2 f1 = __half22float2(*reinterpret_cast<__half2*>(&raw.y));
            ax = fmaf(v, f0.x, ax); ay = fmaf(v, f0.y, ay);
            az = fmaf(v, f1.x, az); aw = fmaf(v, f1.y, aw);
        }
    }
    for (; e < end; e++) {
        uint2 cv = g_csr[e];
        float v = __uint_as_float(cv.y);
        uint2 raw = *reinterpret_cast<const uint2*>(&support[(size_t)cv.x * F + off]);
        float2 f0 = __half22float2(*reinterpret_cast<__half2*>(&raw.x));
        float2 f1 = __half22float2(*reinterpret_cast<__half2*>(&raw.y));
        ax = fmaf(v, f0.x, ax); ay = fmaf(v, f0.y, ay);
        az = fmaf(v, f1.x, az); aw = fmaf(v, f1.y, aw);
    }

    float4 b = *reinterpret_cast<const float4*>(&bias[off]);
    ax = fmaxf(ax + b.x, 0.f); ay = fmaxf(ay + b.y, 0.f);
    az = fmaxf(az + b.z, 0.f); aw = fmaxf(aw + b.w, 0.f);
    *reinterpret_cast<float4*>(&out[(size_t)gw * F + off]) = make_float4(ax, ay, az, aw);
}

// ---------------------------------------------------------------------------
extern "C" void kernel_launch(void* const* d_in, const int* in_sizes, int n_in,
                              void* d_out, int out_size) {
    const float* x  = (const float*)d_in[0];   // [100000, 256]
    const int*   ei = (const int*)  d_in[1];   // [2, 3200000]
    const float* ev = (const float*)d_in[2];   // [3200000]
    const float* W1 = (const float*)d_in[3];   // [256,128]
    const float* b1 = (const float*)d_in[4];
    const float* W2 = (const float*)d_in[5];   // [128,128]
    const float* b2 = (const float*)d_in[6];
    const float* W3 = (const float*)d_in[7];   // [128,128]
    const float* b3 = (const float*)d_in[8];
    float* out = (float*)d_out;                // [4, 100000, 128]

    __half* support = nullptr;
    float*  h       = nullptr;
    cudaGetSymbolAddress((void**)&support, g_support);
    cudaGetSymbolAddress((void**)&h,       g_h);

    // --- build CSR (reused by all 5 SPMMs) ---
    k_zero_counts<<<(N_NODES + 255) / 256, 256>>>();
    k_hist<<<(N_EDGES + 255) / 256, 256>>>(ei);
    k_scan<<<1, 1024>>>();
    k_scatter<<<(N_EDGES + 255) / 256, 256>>>(ei, ev);

    const int gemmGrid = (N_NODES + 127) / 128;
    const int spmmGrid = (N_NODES * 32 + 255) / 256;

    // layer 1: h = relu(spmm(x @ W1) + b1)
    k_gemm<<<gemmGrid, 256>>>(x, W1, support, N_NODES, 256);
    k_spmm<<<spmmGrid, 256>>>(support, b1, h);

    // layer 2: preds[0] = relu(spmm(h @ W2) + b2)
    k_gemm<<<gemmGrid, 256>>>(h, W2, support, N_NODES, 128);
    k_spmm<<<spmmGrid, 256>>>(support, b2, out);

    // timepoints 1..3: preds[t] = relu(spmm(preds[t-1] @ W3) + b3)
    for (int t = 1; t < T_POINTS; t++) {
        const float* prev = out + (size_t)(t - 1) * N_NODES * F;
        float* cur        = out + (size_t)t       * N_NODES * F;
        k_gemm<<<gemmGrid, 256>>>(prev, W3, support, N_NODES, 128);
        k_spmm<<<spmmGrid, 256>>>(support, b3, cur);
    }
}

// round 4
// speedup vs baseline: 1.5958x; 1.3619x over previous
#include <cuda_runtime.h>
#include <cuda_fp16.h>
#include <stdint.h>

#define N_NODES 100000
#define N_EDGES 3200000
#define F 128
#define T_POINTS 4

// ---- scratch (device globals; no allocations allowed) ----
__device__ __half g_xh[(size_t)N_NODES * 256];     // x in fp16 (51.2 MB)
__device__ __half g_support[(size_t)N_NODES * F];  // GEMM output / SPMM gather src (25.6 MB)
__device__ __half g_hh[(size_t)N_NODES * F];       // fp16 copy of layer output -> next GEMM A (25.6 MB)
__device__ __half g_W1h[256 * 128];
__device__ __half g_W2h[128 * 128];
__device__ __half g_W3h[128 * 128];
__device__ int    g_rowptr[N_NODES + 1];
__device__ int    g_deg[N_NODES];
__device__ int    g_cursor[N_NODES];
__device__ uint2  g_csr[N_EDGES];                  // {src col, val bits} (25.6 MB)

// ---------------------------------------------------------------------------
// fp32 -> fp16 conversion
// ---------------------------------------------------------------------------
__global__ void __launch_bounds__(256, 1)
k_f2h(const float* __restrict__ in, __half* __restrict__ out, int n) {
    int i = blockIdx.x * blockDim.x + threadIdx.x;
    int i4 = i * 4;
    if (i4 + 3 < n) {
        float4 v = *reinterpret_cast<const float4*>(&in[i4]);
        __half2 p0 = __floats2half2_rn(v.x, v.y);
        __half2 p1 = __floats2half2_rn(v.z, v.w);
        uint2 packed;
        packed.x = *reinterpret_cast<uint32_t*>(&p0);
        packed.y = *reinterpret_cast<uint32_t*>(&p1);
        *reinterpret_cast<uint2*>(&out[i4]) = packed;
    } else {
        for (int k = i4; k < n; k++) out[k] = __float2half_rn(in[k]);
    }
}

// ---------------------------------------------------------------------------
// CSR build: histogram -> single-block scan -> scatter
// ---------------------------------------------------------------------------
__global__ void __launch_bounds__(256, 1) k_zero_counts() {
    int i = blockIdx.x * blockDim.x + threadIdx.x;
    if (i < N_NODES) { g_deg[i] = 0; g_cursor[i] = 0; }
}

__global__ void __launch_bounds__(256, 1) k_hist(const int* __restrict__ ei) {
    int e = blockIdx.x * blockDim.x + threadIdx.x;
    if (e < N_EDGES) atomicAdd(&g_deg[ei[e]], 1);
}

__global__ void __launch_bounds__(1024, 1) k_scan() {
    __shared__ int sums[1024];
    const int tid = threadIdx.x;
    const int PER = (N_NODES + 1023) / 1024;
    const int base = tid * PER;
    int s = 0;
    #pragma unroll 1
    for (int i = 0; i < PER; i++) {
        int idx = base + i;
        if (idx < N_NODES) s += g_deg[idx];
    }
    sums[tid] = s;
    __syncthreads();
    #pragma unroll 1
    for (int off = 1; off < 1024; off <<= 1) {
        int v = (tid >= off) ? sums[tid - off] : 0;
        __syncthreads();
        sums[tid] += v;
        __syncthreads();
    }
    int run = (tid == 0) ? 0 : sums[tid - 1];
    #pragma unroll 1
    for (int i = 0; i < PER; i++) {
        int idx = base + i;
        if (idx < N_NODES) { g_rowptr[idx] = run; run += g_deg[idx]; }
    }
    if (tid == 0) g_rowptr[N_NODES] = N_EDGES;
}

__global__ void __launch_bounds__(256, 1)
k_scatter(const int* __restrict__ ei, const float* __restrict__ ev) {
    int e = blockIdx.x * blockDim.x + threadIdx.x;
    if (e < N_EDGES) {
        int dst = ei[e];
        int src = ei[N_EDGES + e];
        int pos = g_rowptr[dst] + atomicAdd(&g_cursor[dst], 1);
        g_csr[pos] = make_uint2((unsigned)src, __float_as_uint(ev[e]));
    }
}

// ---------------------------------------------------------------------------
// HMMA GEMM: C[M,128](fp16) = A[M,K](fp16) @ B[K,128](fp16), fp32 accumulate
// 256 threads = 8 warps; block tile 128(M) x 128(N); warp tile 16 x 128
// ---------------------------------------------------------------------------
#define A_STRIDE 24    // halves per A smem row (16 + 8 pad, 48B -> conflict-free LDSM)
#define B_STRIDE 136   // halves per B smem row (128 + 8 pad, 272B)

__global__ void __launch_bounds__(256)
k_gemm_hmma(const __half* __restrict__ A, const __half* __restrict__ B,
            __half* __restrict__ C, int M, int K) {
    __shared__ __half As[128 * A_STRIDE];
    __shared__ __half Bs[16 * B_STRIDE];

    const int tid  = threadIdx.x;
    const int warp = tid >> 5;
    const int lane = tid & 31;
    const int blockRow = blockIdx.x * 128;
    const int warpRow  = warp * 16;

    float c[16][4];
    #pragma unroll
    for (int j = 0; j < 16; j++)
        #pragma unroll
        for (int q = 0; q < 4; q++) c[j][q] = 0.f;

    // ldmatrix source addresses (per-lane)
    const int aRow = warpRow + ((lane >> 3) & 1) * 8 + (lane & 7);
    const int aCol = (lane >> 4) * 8;
    const uint32_t aAddr =
        (uint32_t)__cvta_generic_to_shared(&As[aRow * A_STRIDE + aCol]);
    const int bRow  = ((lane >> 3) & 1) * 8 + (lane & 7);
    const int bColX = (lane >> 4) * 8;

    // global load indices
    const int lar = tid >> 1,  lac = (tid & 1) * 8;   // A: 128 rows x 16 halves
    const int lbr = tid >> 4,  lbc = (tid & 15) * 8;  // B: 16 rows x 128 halves
    const int gra = blockRow + lar;

    for (int k0 = 0; k0 < K; k0 += 16) {
        uint4 va = make_uint4(0, 0, 0, 0);
        if (gra < M)
            va = *reinterpret_cast<const uint4*>(&A[(size_t)gra * K + k0 + lac]);
        *reinterpret_cast<uint4*>(&As[lar * A_STRIDE + lac]) = va;
        *reinterpret_cast<uint4*>(&Bs[lbr * B_STRIDE + lbc]) =
            *reinterpret_cast<const uint4*>(&B[(size_t)(k0 + lbr) * 128 + lbc]);
        __syncthreads();

        uint32_t a0, a1, a2, a3;
        asm volatile("ldmatrix.sync.aligned.m8n8.x4.shared.b16 {%0,%1,%2,%3}, [%4];"
                     : "=r"(a0), "=r"(a1), "=r"(a2), "=r"(a3) : "r"(aAddr));

        #pragma unroll
        for (int j = 0; j < 8; j++) {
            uint32_t b0, b1, b2, b3;
            uint32_t bAddr = (uint32_t)__cvta_generic_to_shared(
                &Bs[bRow * B_STRIDE + j * 16 + bColX]);
            asm volatile("ldmatrix.sync.aligned.m8n8.x4.trans.shared.b16 {%0,%1,%2,%3}, [%4];"
                         : "=r"(b0), "=r"(b1), "=r"(b2), "=r"(b3) : "r"(bAddr));
            asm volatile("mma.sync.aligned.m16n8k16.row.col.f32.f16.f16.f32 "
                         "{%0,%1,%2,%3},{%4,%5,%6,%7},{%8,%9},{%0,%1,%2,%3};"
                         : "+f"(c[2*j][0]), "+f"(c[2*j][1]), "+f"(c[2*j][2]), "+f"(c[2*j][3])
                         : "r"(a0), "r"(a1), "r"(a2), "r"(a3), "r"(b0), "r"(b1));
            asm volatile("mma.sync.aligned.m16n8k16.row.col.f32.f16.f16.f32 "
                         "{%0,%1,%2,%3},{%4,%5,%6,%7},{%8,%9},{%0,%1,%2,%3};"
                         : "+f"(c[2*j+1][0]), "+f"(c[2*j+1][1]), "+f"(c[2*j+1][2]), "+f"(c[2*j+1][3])
                         : "r"(a0), "r"(a1), "r"(a2), "r"(a3), "r"(b2), "r"(b3));
        }
        __syncthreads();
    }

    // epilogue: fp32 acc -> fp16 C
    const int row0 = blockRow + warpRow + (lane >> 2);
    const int row1 = row0 + 8;
    #pragma unroll
    for (int j = 0; j < 16; j++) {
        int col = j * 8 + (lane & 3) * 2;
        if (row0 < M) {
            __half2 p = __floats2half2_rn(c[j][0], c[j][1]);
            *reinterpret_cast<uint32_t*>(&C[(size_t)row0 * 128 + col]) =
                *reinterpret_cast<uint32_t*>(&p);
        }
        if (row1 < M) {
            __half2 p = __floats2half2_rn(c[j][2], c[j][3]);
            *reinterpret_cast<uint32_t*>(&C[(size_t)row1 * 128 + col]) =
                *reinterpret_cast<uint32_t*>(&p);
        }
    }
}

// ---------------------------------------------------------------------------
// SPMM (CSR gather, fp16 src, fp32 accum) + bias + ReLU
// writes fp16 copy (next GEMM input) and optionally fp32 (d_out slice)
// ---------------------------------------------------------------------------
__global__ void __launch_bounds__(256, 4)
k_spmm(const __half* __restrict__ support,
       const float* __restrict__ bias,
       float* __restrict__ out32,        // may be null
       __half* __restrict__ out16) {
    int gw = (blockIdx.x * blockDim.x + threadIdx.x) >> 5;
    int lane = threadIdx.x & 31;
    if (gw >= N_NODES) return;

    int e   = g_rowptr[gw];
    int end = g_rowptr[gw + 1];

    float ax = 0.f, ay = 0.f, az = 0.f, aw = 0.f;
    const int off = lane * 4;

    for (; e + 4 <= end; e += 4) {
        #pragma unroll
        for (int u = 0; u < 4; u++) {
            uint2 cv = g_csr[e + u];
            float v = __uint_as_float(cv.y);
            uint2 raw = *reinterpret_cast<const uint2*>(&support[(size_t)cv.x * F + off]);
            float2 f0 = __half22float2(*reinterpret_cast<__half2*>(&raw.x));
            float2 f1 = __half22float2(*reinterpret_cast<__half2*>(&raw.y));
            ax = fmaf(v, f0.x, ax); ay = fmaf(v, f0.y, ay);
            az = fmaf(v, f1.x, az); aw = fmaf(v, f1.y, aw);
        }
    }
    for (; e < end; e++) {
        uint2 cv = g_csr[e];
        float v = __uint_as_float(cv.y);
        uint2 raw = *reinterpret_cast<const uint2*>(&support[(size_t)cv.x * F + off]);
        float2 f0 = __half22float2(*reinterpret_cast<__half2*>(&raw.x));
        float2 f1 = __half22float2(*reinterpret_cast<__half2*>(&raw.y));
        ax = fmaf(v, f0.x, ax); ay = fmaf(v, f0.y, ay);
        az = fmaf(v, f1.x, az); aw = fmaf(v, f1.y, aw);
    }

    float4 b = *reinterpret_cast<const float4*>(&bias[off]);
    ax = fmaxf(ax + b.x, 0.f); ay = fmaxf(ay + b.y, 0.f);
    az = fmaxf(az + b.z, 0.f); aw = fmaxf(aw + b.w, 0.f);

    if (out32)
        *reinterpret_cast<float4*>(&out32[(size_t)gw * F + off]) =
            make_float4(ax, ay, az, aw);

    __half2 p0 = __floats2half2_rn(ax, ay);
    __half2 p1 = __floats2half2_rn(az, aw);
    uint2 packed;
    packed.x = *reinterpret_cast<uint32_t*>(&p0);
    packed.y = *reinterpret_cast<uint32_t*>(&p1);
    *reinterpret_cast<uint2*>(&out16[(size_t)gw * F + off]) = packed;
}

// ---------------------------------------------------------------------------
extern "C" void kernel_launch(void* const* d_in, const int* in_sizes, int n_in,
                              void* d_out, int out_size) {
    const float* x  = (const float*)d_in[0];
    const int*   ei = (const int*)  d_in[1];
    const float* ev = (const float*)d_in[2];
    const float* W1 = (const float*)d_in[3];
    const float* b1 = (const float*)d_in[4];
    const float* W2 = (const float*)d_in[5];
    const float* b2 = (const float*)d_in[6];
    const float* W3 = (const float*)d_in[7];
    const float* b3 = (const float*)d_in[8];
    float* out = (float*)d_out;

    __half *xh, *support, *hh, *W1h, *W2h, *W3h;
    cudaGetSymbolAddress((void**)&xh,      g_xh);
    cudaGetSymbolAddress((void**)&support, g_support);
    cudaGetSymbolAddress((void**)&hh,      g_hh);
    cudaGetSymbolAddress((void**)&W1h,     g_W1h);
    cudaGetSymbolAddress((void**)&W2h,     g_W2h);
    cudaGetSymbolAddress((void**)&W3h,     g_W3h);

    // fp32 -> fp16 conversions
    k_f2h<<<(N_NODES * 256 / 4 + 255) / 256, 256>>>(x, xh, N_NODES * 256);
    k_f2h<<<(256 * 128 / 4 + 255) / 256, 256>>>(W1, W1h, 256 * 128);
    k_f2h<<<(128 * 128 / 4 + 255) / 256, 256>>>(W2, W2h, 128 * 128);
    k_f2h<<<(128 * 128 / 4 + 255) / 256, 256>>>(W3, W3h, 128 * 128);

    // CSR build (reused by all 5 SPMMs)
    k_zero_counts<<<(N_NODES + 255) / 256, 256>>>();
    k_hist<<<(N_EDGES + 255) / 256, 256>>>(ei);
    k_scan<<<1, 1024>>>();
    k_scatter<<<(N_EDGES + 255) / 256, 256>>>(ei, ev);

    const int gemmGrid = (N_NODES + 127) / 128;
    const int spmmGrid = (N_NODES * 32 + 255) / 256;

    // layer 1: hh = relu(spmm(x @ W1) + b1)   (fp16 only — feeds GEMM 2)
    k_gemm_hmma<<<gemmGrid, 256>>>(xh, W1h, support, N_NODES, 256);
    k_spmm<<<spmmGrid, 256>>>(support, b1, nullptr, hh);

    // layer 2: preds[0]
    k_gemm_hmma<<<gemmGrid, 256>>>(hh, W2h, support, N_NODES, 128);
    k_spmm<<<spmmGrid, 256>>>(support, b2, out, hh);

    // timepoints 1..3
    for (int t = 1; t < T_POINTS; t++) {
        float* cur = out + (size_t)t * N_NODES * F;
        k_gemm_hmma<<<gemmGrid, 256>>>(hh, W3h, support, N_NODES, 128);
        k_spmm<<<spmmGrid, 256>>>(support, b3, cur, hh);
    }
}